// round 14
// baseline (speedup 1.0000x reference)
#include <cuda_runtime.h>
#include <stdint.h>

// Problem constants
#define BATCH 16
#define LQ 2048
#define LK 2048
#define DH 64

// Block = 64 q-rows x full LK, k-tiles of 64. 256 threads (8 warps).
// wg = w&3 -> rows wg*16..+16, nh = w>>2 -> attn cols nh*32..+32.
// Double-buffered cp.async pipeline; B = raw fp32 bits as tf32 (truncation),
// bias cancelled via A-scale; C (0.125*log2e) folded into A so accumulators
// are scaled scores directly usable by ex2.
#define BQ 64
#define BK 64
#define NT 256
#define NTILES (LK / BK)     // 32
#define KPAD 72              // fp32 k row stride: LDS.64 conflict-free

#define OUT_ELEMS  ((size_t)BATCH * LQ * DH)   // 2,097,152
#define ATTN_ELEMS ((size_t)BATCH * LQ * LK)   // 67,108,864

#define CSCALE 0.18033688011112042f            // 0.125 * log2(e)
#define TRUNC_CORR 1.000338f                   // 1 + 2^-11 * ln2
#define EPS_S (0.08f * CSCALE)                 // repair threshold, scaled units

__device__ __forceinline__ float ex2a(float x) {
    float r; asm("ex2.approx.ftz.f32 %0, %1;" : "=f"(r) : "f"(x)); return r;
}
__device__ __forceinline__ unsigned cvt_tf32(float x) {
    unsigned r; asm("cvt.rna.tf32.f32 %0, %1;" : "=r"(r) : "f"(x)); return r;
}
__device__ __forceinline__ void mma_tf32(float c[4],
                                         unsigned a0, unsigned a1, unsigned a2, unsigned a3,
                                         unsigned b0, unsigned b1) {
    asm volatile("mma.sync.aligned.m16n8k8.row.col.f32.tf32.tf32.f32 "
                 "{%0,%1,%2,%3}, {%4,%5,%6,%7}, {%8,%9}, {%0,%1,%2,%3};"
                 : "+f"(c[0]), "+f"(c[1]), "+f"(c[2]), "+f"(c[3])
                 : "r"(a0), "r"(a1), "r"(a2), "r"(a3), "r"(b0), "r"(b1));
}
__device__ __forceinline__ void cp_async16(uint32_t dst_smem, const void* src) {
    asm volatile("cp.async.cg.shared.global [%0], [%1], 16;"
                 :: "r"(dst_smem), "l"(src) : "memory");
}
#define CP_COMMIT() asm volatile("cp.async.commit_group;" ::: "memory")
#define CP_WAIT0()  asm volatile("cp.async.wait_group 0;" ::: "memory")

__global__ __launch_bounds__(NT)
void wta_attn14_kernel(const float* __restrict__ q,
                       const float* __restrict__ k,
                       const float* __restrict__ v,
                       float* __restrict__ out,
                       int write_out, int write_attn, long long attn_off)
{
    __shared__ float ks[2][BK][KPAD];          // 36.9 KB
    __shared__ float tilemax[BQ][NTILES];      //  8  KB (scaled units)
    __shared__ float tmstage[2][2][BQ];
    __shared__ float rs[2][BQ];
    __shared__ float rowsum[BQ];
    __shared__ float pval[BQ];
    __shared__ int   widx[BQ];

    const int b    = blockIdx.y;
    const int q0   = blockIdx.x * BQ;
    const int tid  = threadIdx.x;
    const int w    = tid >> 5;
    const int lane = tid & 31;
    const int wg   = w & 3;
    const int nh   = w >> 2;
    const int l4   = lane >> 2;
    const int lm   = lane & 3;

    const float* qb = q + ((size_t)b * LQ + q0) * DH;
    const float* kb = k + (size_t)b * LK * DH;

    const int r0 = wg * 16 + l4;
    const int r1 = r0 + 8;

    // ---- A fragments: permuted K-index + folded C*TRUNC_CORR scale ----
    const float CC = CSCALE * TRUNC_CORR;
    unsigned Af[8][4];
    #pragma unroll
    for (int s = 0; s < 8; s++) {
        Af[s][0] = cvt_tf32(CC * qb[(size_t)r0 * DH + s * 8 + 2 * lm]);
        Af[s][1] = cvt_tf32(CC * qb[(size_t)r1 * DH + s * 8 + 2 * lm]);
        Af[s][2] = cvt_tf32(CC * qb[(size_t)r0 * DH + s * 8 + 2 * lm + 1]);
        Af[s][3] = cvt_tf32(CC * qb[(size_t)r1 * DH + s * 8 + 2 * lm + 1]);
    }

    float sum0 = 0.0f, sum1 = 0.0f;

    float4* az = 0;
    if (write_attn)
        az = (float4*)(out + attn_off + ((size_t)b * LQ + q0) * LK);

    uint32_t dst[2][4];
    #pragma unroll
    for (int i = 0; i < 4; i++) {
        int fi   = tid + i * NT;
        int kr   = fi >> 4;
        int c4   = fi & 15;
        dst[0][i] = (uint32_t)__cvta_generic_to_shared(&ks[0][kr][c4 * 4]);
        dst[1][i] = (uint32_t)__cvta_generic_to_shared(&ks[1][kr][c4 * 4]);
    }

    // ---- prologue: tile 0 -> buffer 0 ----
    #pragma unroll
    for (int i = 0; i < 4; i++) {
        int fi = tid + i * NT;
        cp_async16(dst[0][i], kb + (size_t)fi * 4);
    }
    CP_COMMIT();
    CP_WAIT0();
    __syncthreads();

    // ================= mainloop =================
    for (int t = 0; t < NTILES; t++) {
        const int cur = t & 1;

        if (t + 1 < NTILES) {
            const float* src = kb + (size_t)(t + 1) * BK * DH;
            #pragma unroll
            for (int i = 0; i < 4; i++) {
                int fi = tid + i * NT;
                cp_async16(dst[cur ^ 1][i], src + (size_t)fi * 4);
            }
            CP_COMMIT();
        }

        if (t > 0 && tid < BQ)
            tilemax[tid][t - 1] = fmaxf(tmstage[cur ^ 1][0][tid],
                                        tmstage[cur ^ 1][1][tid]);

        float acc[4][4];
        #pragma unroll
        for (int nc = 0; nc < 4; nc++)
            #pragma unroll
            for (int c = 0; c < 4; c++) acc[nc][c] = 0.0f;

        #pragma unroll
        for (int nc = 0; nc < 4; nc++) {
            const float* rp = &ks[cur][nh * 32 + nc * 8 + l4][lm * 2];
            #pragma unroll
            for (int s = 0; s < 8; s++) {
                unsigned long long bv = *(const unsigned long long*)(rp + s * 8);
                mma_tf32(acc[nc], Af[s][0], Af[s][1], Af[s][2], Af[s][3],
                         (unsigned)(bv & 0xffffffffu), (unsigned)(bv >> 32));
            }
        }

        // epilogue: max + exp-sum (acc already scaled)
        float tm0 = -1e30f, tm1 = -1e30f;
        #pragma unroll
        for (int nc = 0; nc < 4; nc++) {
            tm0 = fmaxf(tm0, fmaxf(acc[nc][0], acc[nc][1]));
            tm1 = fmaxf(tm1, fmaxf(acc[nc][2], acc[nc][3]));
            sum0 += ex2a(acc[nc][0]) + ex2a(acc[nc][1]);
            sum1 += ex2a(acc[nc][2]) + ex2a(acc[nc][3]);
        }
        #pragma unroll
        for (int off = 1; off <= 2; off <<= 1) {
            tm0 = fmaxf(tm0, __shfl_xor_sync(0xffffffffu, tm0, off));
            tm1 = fmaxf(tm1, __shfl_xor_sync(0xffffffffu, tm1, off));
        }
        if (lm == 0) { tmstage[cur][nh][r0] = tm0; tmstage[cur][nh][r1] = tm1; }

        if (write_attn) {
            float4* azc = az + (size_t)t * (BQ * BK / 4);
            #pragma unroll
            for (int j = 0; j < 4; j++)
                azc[tid + j * NT] = make_float4(0.f, 0.f, 0.f, 0.f);
        }

        if (t + 1 < NTILES) CP_WAIT0();
        __syncthreads();
    }
    if (tid < BQ)
        tilemax[tid][NTILES - 1] = fmaxf(tmstage[(NTILES - 1) & 1][0][tid],
                                         tmstage[(NTILES - 1) & 1][1][tid]);

    #pragma unroll
    for (int off = 1; off <= 2; off <<= 1) {
        sum0 += __shfl_xor_sync(0xffffffffu, sum0, off);
        sum1 += __shfl_xor_sync(0xffffffffu, sum1, off);
    }
    if (lm == 0) { rs[nh][r0] = sum0; rs[nh][r1] = sum1; }
    __syncthreads();

    if (tid < BQ) rowsum[tid] = rs[0][tid] + rs[1][tid];
    __syncthreads();

    // ================= repair: warp/row, 4 cols per round, 8-lane dots =================
    const int colgrp = lane >> 3;      // 0..3
    const int sub    = lane & 7;       // 0..7: covers d = sub*8 .. sub*8+7
    #pragma unroll 1
    for (int rr8 = 0; rr8 < BQ / 8; rr8++) {
        const int r = w * 8 + rr8;

        const float tmv = tilemax[r][lane];
        float best = tmv;
        #pragma unroll
        for (int off = 16; off > 0; off >>= 1)
            best = fmaxf(best, __shfl_xor_sync(0xffffffffu, best, off));
        const float thr = best - EPS_S;

        // q chunk for this lane: 8 floats
        const float4 qa = *(const float4*)(qb + (size_t)r * DH + sub * 8);
        const float4 qc = *(const float4*)(qb + (size_t)r * DH + sub * 8 + 4);

        float bm = -1e30f;
        int   bi = 0;
        #pragma unroll 1
        for (int t = 0; t < NTILES; t++) {
            if (__shfl_sync(0xffffffffu, tmv, t) < thr) continue;   // warp-uniform
            const float* kt = kb + (size_t)t * BK * DH;
            #pragma unroll 4
            for (int rr = 0; rr < 16; rr++) {
                const int col = rr * 4 + colgrp;
                const float* kp = kt + (size_t)col * DH + sub * 8;
                const float4 ka = *(const float4*)kp;
                const float4 kc = *(const float4*)(kp + 4);
                float p = fmaf(qa.x, ka.x, fmaf(qa.y, ka.y,
                          fmaf(qa.z, ka.z, qa.w * ka.w)));
                p = fmaf(qc.x, kc.x, fmaf(qc.y, kc.y,
                    fmaf(qc.z, kc.z, fmaf(qc.w, kc.w, p))));
                // reduce within the 8 lanes of this column group
                p += __shfl_xor_sync(0xffffffffu, p, 4, 8);
                p += __shfl_xor_sync(0xffffffffu, p, 2, 8);
                p += __shfl_xor_sync(0xffffffffu, p, 1, 8);
                if (p > bm) { bm = p; bi = t * BK + col; }  // strict >: lowest rr kept
            }
        }
        // final reduce across all 32 lanes (tie -> lower idx)
        #pragma unroll
        for (int off = 16; off > 0; off >>= 1) {
            float om = __shfl_xor_sync(0xffffffffu, bm, off);
            int   oi = __shfl_xor_sync(0xffffffffu, bi, off);
            if (om > bm || (om == bm && oi < bi)) { bm = om; bi = oi; }
        }
        if (lane == 0) {
            float p = ex2a(bm * CSCALE) / rowsum[r];
            pval[r] = p;
            widx[r] = bi;
            if (write_attn)
                out[attn_off + ((size_t)b * LQ + q0 + r) * LK + bi] = p;
        }
    }
    __syncthreads();

    // ================= dense output =================
    if (write_out) {
        #pragma unroll
        for (int i = tid; i < BQ * (DH / 4); i += NT) {
            const int r = i >> 4;
            const int c = i & 15;
            const float p = pval[r];
            const float4 vv = *(const float4*)(v + ((size_t)b * LK + widx[r]) * DH + c * 4);
            float4 o;
            o.x = p * vv.x; o.y = p * vv.y; o.z = p * vv.z; o.w = p * vv.w;
            *(float4*)(out + ((size_t)b * LQ + q0 + r) * DH + c * 4) = o;
        }
    }
}

extern "C" void kernel_launch(void* const* d_in, const int* in_sizes, int n_in,
                              void* d_out, int out_size)
{
    const float* q = (const float*)d_in[0];
    const float* k = (const float*)d_in[1];
    const float* v = (const float*)d_in[2];
    float* out = (float*)d_out;

    int wout = 0, wattn = 0;
    long long aoff = 0;
    size_t osz = (size_t)out_size;
    if (osz == OUT_ELEMS + ATTN_ELEMS) { wout = 1; wattn = 1; aoff = (long long)OUT_ELEMS; }
    else if (osz == ATTN_ELEMS)        { wattn = 1; aoff = 0; }
    else                               { wout = 1; }

    dim3 grid(LQ / BQ, BATCH);
    wta_attn14_kernel<<<grid, NT>>>(q, k, v, out, wout, wattn, aoff);
}

// round 15
// speedup vs baseline: 1.4678x; 1.4678x over previous
#include <cuda_runtime.h>
#include <stdint.h>

// Problem constants
#define BATCH 16
#define LQ 2048
#define LK 2048
#define DH 64

// Block = 64 q-rows x full LK, k-tiles of 64. 256 threads (8 warps).
// wg = w&3 -> rows wg*16..+16, nh = w>>2 -> attn cols nh*32..+32.
// Double-buffered cp.async pipeline; B = raw fp32 bits as tf32 (truncation),
// bias cancelled + softmax scale C folded into the A fragments.
// Repair: R13 sector-clean pattern (2 cols/round, 16-lane contiguous float4).
#define BQ 64
#define BK 64
#define NT 256
#define NTILES (LK / BK)     // 32
#define KPAD 72              // fp32 k row stride: LDS.64 conflict-free

#define OUT_ELEMS  ((size_t)BATCH * LQ * DH)   // 2,097,152
#define ATTN_ELEMS ((size_t)BATCH * LQ * LK)   // 67,108,864

#define CSCALE 0.18033688011112042f            // 0.125 * log2(e)
#define TRUNC_CORR 1.000338f                   // 1 + 2^-11 * ln2
#define EPS_S (0.08f * CSCALE)                 // repair threshold (scaled units)

__device__ __forceinline__ float ex2a(float x) {
    float r; asm("ex2.approx.ftz.f32 %0, %1;" : "=f"(r) : "f"(x)); return r;
}
__device__ __forceinline__ unsigned cvt_tf32(float x) {
    unsigned r; asm("cvt.rna.tf32.f32 %0, %1;" : "=r"(r) : "f"(x)); return r;
}
__device__ __forceinline__ void mma_tf32(float c[4],
                                         unsigned a0, unsigned a1, unsigned a2, unsigned a3,
                                         unsigned b0, unsigned b1) {
    asm volatile("mma.sync.aligned.m16n8k8.row.col.f32.tf32.tf32.f32 "
                 "{%0,%1,%2,%3}, {%4,%5,%6,%7}, {%8,%9}, {%0,%1,%2,%3};"
                 : "+f"(c[0]), "+f"(c[1]), "+f"(c[2]), "+f"(c[3])
                 : "r"(a0), "r"(a1), "r"(a2), "r"(a3), "r"(b0), "r"(b1));
}
__device__ __forceinline__ void cp_async16(uint32_t dst_smem, const void* src) {
    asm volatile("cp.async.cg.shared.global [%0], [%1], 16;"
                 :: "r"(dst_smem), "l"(src) : "memory");
}
#define CP_COMMIT() asm volatile("cp.async.commit_group;" ::: "memory")
#define CP_WAIT0()  asm volatile("cp.async.wait_group 0;" ::: "memory")

__global__ __launch_bounds__(NT)
void wta_attn15_kernel(const float* __restrict__ q,
                       const float* __restrict__ k,
                       const float* __restrict__ v,
                       float* __restrict__ out,
                       int write_out, int write_attn, long long attn_off)
{
    __shared__ float ks[2][BK][KPAD];          // 36.9 KB
    __shared__ float tilemax[BQ][NTILES];      //  8  KB (scaled units)
    __shared__ float tmstage[2][2][BQ];
    __shared__ float rs[2][BQ];
    __shared__ float rowsum[BQ];
    __shared__ float pval[BQ];
    __shared__ int   widx[BQ];

    const int b    = blockIdx.y;
    const int q0   = blockIdx.x * BQ;
    const int tid  = threadIdx.x;
    const int w    = tid >> 5;
    const int lane = tid & 31;
    const int wg   = w & 3;
    const int nh   = w >> 2;
    const int l4   = lane >> 2;
    const int lm   = lane & 3;

    const float* qb = q + ((size_t)b * LQ + q0) * DH;
    const float* kb = k + (size_t)b * LK * DH;

    const int r0 = wg * 16 + l4;
    const int r1 = r0 + 8;

    // ---- A fragments: permuted K-index + folded C*TRUNC_CORR scale ----
    const float CC = CSCALE * TRUNC_CORR;
    unsigned Af[8][4];
    #pragma unroll
    for (int s = 0; s < 8; s++) {
        Af[s][0] = cvt_tf32(CC * qb[(size_t)r0 * DH + s * 8 + 2 * lm]);
        Af[s][1] = cvt_tf32(CC * qb[(size_t)r1 * DH + s * 8 + 2 * lm]);
        Af[s][2] = cvt_tf32(CC * qb[(size_t)r0 * DH + s * 8 + 2 * lm + 1]);
        Af[s][3] = cvt_tf32(CC * qb[(size_t)r1 * DH + s * 8 + 2 * lm + 1]);
    }

    float sum0 = 0.0f, sum1 = 0.0f;

    float4* az = 0;
    if (write_attn)
        az = (float4*)(out + attn_off + ((size_t)b * LQ + q0) * LK);

    uint32_t dst[2][4];
    #pragma unroll
    for (int i = 0; i < 4; i++) {
        int fi   = tid + i * NT;
        int kr   = fi >> 4;
        int c4   = fi & 15;
        dst[0][i] = (uint32_t)__cvta_generic_to_shared(&ks[0][kr][c4 * 4]);
        dst[1][i] = (uint32_t)__cvta_generic_to_shared(&ks[1][kr][c4 * 4]);
    }

    // ---- prologue: tile 0 -> buffer 0 ----
    #pragma unroll
    for (int i = 0; i < 4; i++) {
        int fi = tid + i * NT;
        cp_async16(dst[0][i], kb + (size_t)fi * 4);
    }
    CP_COMMIT();
    CP_WAIT0();
    __syncthreads();

    // ================= mainloop: double-buffered pipeline =================
    for (int t = 0; t < NTILES; t++) {
        const int cur = t & 1;

        if (t + 1 < NTILES) {
            const float* src = kb + (size_t)(t + 1) * BK * DH;
            #pragma unroll
            for (int i = 0; i < 4; i++) {
                int fi = tid + i * NT;
                cp_async16(dst[cur ^ 1][i], src + (size_t)fi * 4);
            }
            CP_COMMIT();
        }

        if (t > 0 && tid < BQ)
            tilemax[tid][t - 1] = fmaxf(tmstage[cur ^ 1][0][tid],
                                        tmstage[cur ^ 1][1][tid]);

        float acc[4][4];
        #pragma unroll
        for (int nc = 0; nc < 4; nc++)
            #pragma unroll
            for (int c = 0; c < 4; c++) acc[nc][c] = 0.0f;

        #pragma unroll
        for (int nc = 0; nc < 4; nc++) {
            const float* rp = &ks[cur][nh * 32 + nc * 8 + l4][lm * 2];
            #pragma unroll
            for (int s = 0; s < 8; s++) {
                unsigned long long bv = *(const unsigned long long*)(rp + s * 8);
                mma_tf32(acc[nc], Af[s][0], Af[s][1], Af[s][2], Af[s][3],
                         (unsigned)(bv & 0xffffffffu), (unsigned)(bv >> 32));
            }
        }

        // epilogue: max + exp-sum (acc already scaled)
        float tm0 = -1e30f, tm1 = -1e30f;
        #pragma unroll
        for (int nc = 0; nc < 4; nc++) {
            tm0 = fmaxf(tm0, fmaxf(acc[nc][0], acc[nc][1]));
            tm1 = fmaxf(tm1, fmaxf(acc[nc][2], acc[nc][3]));
            sum0 += ex2a(acc[nc][0]) + ex2a(acc[nc][1]);
            sum1 += ex2a(acc[nc][2]) + ex2a(acc[nc][3]);
        }
        #pragma unroll
        for (int off = 1; off <= 2; off <<= 1) {
            tm0 = fmaxf(tm0, __shfl_xor_sync(0xffffffffu, tm0, off));
            tm1 = fmaxf(tm1, __shfl_xor_sync(0xffffffffu, tm1, off));
        }
        if (lm == 0) { tmstage[cur][nh][r0] = tm0; tmstage[cur][nh][r1] = tm1; }

        if (write_attn) {
            float4* azc = az + (size_t)t * (BQ * BK / 4);
            #pragma unroll
            for (int j = 0; j < 4; j++)
                azc[tid + j * NT] = make_float4(0.f, 0.f, 0.f, 0.f);
        }

        if (t + 1 < NTILES) CP_WAIT0();
        __syncthreads();
    }
    if (tid < BQ)
        tilemax[tid][NTILES - 1] = fmaxf(tmstage[(NTILES - 1) & 1][0][tid],
                                         tmstage[(NTILES - 1) & 1][1][tid]);

    #pragma unroll
    for (int off = 1; off <= 2; off <<= 1) {
        sum0 += __shfl_xor_sync(0xffffffffu, sum0, off);
        sum1 += __shfl_xor_sync(0xffffffffu, sum1, off);
    }
    if (lm == 0) { rs[nh][r0] = sum0; rs[nh][r1] = sum1; }
    __syncthreads();

    if (tid < BQ) rowsum[tid] = rs[0][tid] + rs[1][tid];
    __syncthreads();

    // ===== repair: R13 sector-clean pattern; threshold in scaled units =====
    #pragma unroll 1
    for (int rr8 = 0; rr8 < BQ / 8; rr8++) {
        const int r = w * 8 + rr8;

        const float tmv = tilemax[r][lane];      // 32 lanes = 32 tiles
        float best = tmv;
        #pragma unroll
        for (int off = 16; off > 0; off >>= 1)
            best = fmaxf(best, __shfl_xor_sync(0xffffffffu, best, off));
        const float thr = best - EPS_S;

        const float4 qv = *(const float4*)(qb + (size_t)r * DH + (lane & 15) * 4);

        float bm = -1e30f;
        int   bi = 0;
        #pragma unroll 1
        for (int t = 0; t < NTILES; t++) {
            if (__shfl_sync(0xffffffffu, tmv, t) < thr) continue;   // warp-uniform
            const float* kt = kb + (size_t)t * BK * DH;
            #pragma unroll 4
            for (int rr = 0; rr < 32; rr++) {
                const int col = rr * 2 + (lane >> 4);
                const float4 kv = *(const float4*)(kt + (size_t)col * DH + (lane & 15) * 4);
                float p = fmaf(qv.x, kv.x, fmaf(qv.y, kv.y,
                          fmaf(qv.z, kv.z, qv.w * kv.w)));
                p += __shfl_xor_sync(0xffffffffu, p, 8, 16);
                p += __shfl_xor_sync(0xffffffffu, p, 4, 16);
                p += __shfl_xor_sync(0xffffffffu, p, 2, 16);
                p += __shfl_xor_sync(0xffffffffu, p, 1, 16);
                if (p > bm) { bm = p; bi = t * BK + col; }  // strict > : lowest kept
            }
        }
        #pragma unroll
        for (int off = 16; off > 0; off >>= 1) {
            float om = __shfl_xor_sync(0xffffffffu, bm, off);
            int   oi = __shfl_xor_sync(0xffffffffu, bi, off);
            if (om > bm || (om == bm && oi < bi)) { bm = om; bi = oi; }
        }
        if (lane == 0) {
            float p = ex2a(bm * CSCALE) / rowsum[r];
            pval[r] = p;
            widx[r] = bi;
            if (write_attn)
                out[attn_off + ((size_t)b * LQ + q0 + r) * LK + bi] = p;
        }
    }
    __syncthreads();

    // ================= dense output =================
    if (write_out) {
        #pragma unroll
        for (int i = tid; i < BQ * (DH / 4); i += NT) {
            const int r = i >> 4;
            const int c = i & 15;
            const float p = pval[r];
            const float4 vv = *(const float4*)(v + ((size_t)b * LK + widx[r]) * DH + c * 4);
            float4 o;
            o.x = p * vv.x; o.y = p * vv.y; o.z = p * vv.z; o.w = p * vv.w;
            *(float4*)(out + ((size_t)b * LQ + q0 + r) * DH + c * 4) = o;
        }
    }
}

extern "C" void kernel_launch(void* const* d_in, const int* in_sizes, int n_in,
                              void* d_out, int out_size)
{
    const float* q = (const float*)d_in[0];
    const float* k = (const float*)d_in[1];
    const float* v = (const float*)d_in[2];
    float* out = (float*)d_out;

    int wout = 0, wattn = 0;
    long long aoff = 0;
    size_t osz = (size_t)out_size;
    if (osz == OUT_ELEMS + ATTN_ELEMS) { wout = 1; wattn = 1; aoff = (long long)OUT_ELEMS; }
    else if (osz == ATTN_ELEMS)        { wattn = 1; aoff = 0; }
    else                               { wout = 1; }

    dim3 grid(LQ / BQ, BATCH);
    wta_attn15_kernel<<<grid, NT>>>(q, k, v, out, wout, wattn, aoff);
}

// round 16
// speedup vs baseline: 1.5238x; 1.0381x over previous
#include <cuda_runtime.h>
#include <cuda_bf16.h>
#include <stdint.h>

// Problem constants
#define BATCH 16
#define LQ 2048
#define LK 2048
#define DH 64

#define BQ 64
#define BK 64
#define NT 256
#define NTILES (LK / BK)     // 32
#define KROWB 80             // bf16 k row stride (160 B): LDS.64 conflict-free per phase

#define OUT_ELEMS  ((size_t)BATCH * LQ * DH)   // 2,097,152
#define ATTN_ELEMS ((size_t)BATCH * LQ * LK)   // 67,108,864

#define CSCALE 0.18033688011112042f            // 0.125 * log2(e)
#define EPS_S (0.15f * CSCALE)                 // repair threshold (scaled units, 11-sigma bf16)

// 4 MB bf16 copy of K (rna conversion; unbiased) — device scratch is allowed.
__device__ __align__(16) __nv_bfloat16 g_kbf[(size_t)BATCH * LK * DH];

__device__ __forceinline__ float ex2a(float x) {
    float r; asm("ex2.approx.ftz.f32 %0, %1;" : "=f"(r) : "f"(x)); return r;
}
__device__ __forceinline__ unsigned pack_bf2(float lo, float hi) {
    __nv_bfloat162 t = __floats2bfloat162_rn(lo, hi);   // .x = lo (low 16 bits)
    return *(unsigned*)&t;
}
__device__ __forceinline__ void mma_bf16(float c[4],
                                         unsigned a0, unsigned a1, unsigned a2, unsigned a3,
                                         unsigned b0, unsigned b1) {
    asm volatile("mma.sync.aligned.m16n8k16.row.col.f32.bf16.bf16.f32 "
                 "{%0,%1,%2,%3}, {%4,%5,%6,%7}, {%8,%9}, {%0,%1,%2,%3};"
                 : "+f"(c[0]), "+f"(c[1]), "+f"(c[2]), "+f"(c[3])
                 : "r"(a0), "r"(a1), "r"(a2), "r"(a3), "r"(b0), "r"(b1));
}
__device__ __forceinline__ void cp_async16(uint32_t dst_smem, const void* src) {
    asm volatile("cp.async.cg.shared.global [%0], [%1], 16;"
                 :: "r"(dst_smem), "l"(src) : "memory");
}
#define CP_COMMIT() asm volatile("cp.async.commit_group;" ::: "memory")
#define CP_WAIT0()  asm volatile("cp.async.wait_group 0;" ::: "memory")

// ---------- pre-pass: K fp32 -> bf16 (rna) ----------
__global__ __launch_bounds__(256)
void cvt_k_kernel(const float* __restrict__ k)
{
    size_t i = (size_t)blockIdx.x * blockDim.x + threadIdx.x;   // 524288 threads x 4 elems
    float4 w = ((const float4*)k)[i];
    __nv_bfloat162 lo = __floats2bfloat162_rn(w.x, w.y);
    __nv_bfloat162 hi = __floats2bfloat162_rn(w.z, w.w);
    ((__nv_bfloat162*)g_kbf)[i * 2 + 0] = lo;
    ((__nv_bfloat162*)g_kbf)[i * 2 + 1] = hi;
}

__global__ __launch_bounds__(NT)
void wta_attn16_kernel(const float* __restrict__ q,
                       const float* __restrict__ k,
                       const float* __restrict__ v,
                       float* __restrict__ out,
                       int write_out, int write_attn, long long attn_off)
{
    __shared__ __nv_bfloat16 ks[2][BK][KROWB]; // 20.5 KB double-buffered bf16 k tiles
    __shared__ float tilemax[BQ][NTILES];      //  8  KB (scaled units)
    __shared__ float tmstage[2][2][BQ];
    __shared__ float rs[2][BQ];
    __shared__ float rowsum[BQ];
    __shared__ float pval[BQ];
    __shared__ int   widx[BQ];

    const int b    = blockIdx.y;
    const int q0   = blockIdx.x * BQ;
    const int tid  = threadIdx.x;
    const int w    = tid >> 5;
    const int lane = tid & 31;
    const int wg   = w & 3;        // row group
    const int nh   = w >> 2;       // col half
    const int l4   = lane >> 2;
    const int lm   = lane & 3;

    const float* qb = q + ((size_t)b * LQ + q0) * DH;
    const float* kb = k + (size_t)b * LK * DH;
    const __nv_bfloat16* kbf = g_kbf + (size_t)b * LK * DH;

    const int r0 = wg * 16 + l4;
    const int r1 = r0 + 8;

    // ---- A fragments (bf16, C folded, permuted K-index) ----
    // slice s covers physical d [16s,16s+16); this thread's B words are d {4lm..4lm+3}.
    // a0/a1 pair with d{4lm,4lm+1}, a2/a3 with d{4lm+2,4lm+3}.
    unsigned Af[4][4];
    #pragma unroll
    for (int s = 0; s < 4; s++) {
        const float* p0 = qb + (size_t)r0 * DH + s * 16 + 4 * lm;
        const float* p1 = qb + (size_t)r1 * DH + s * 16 + 4 * lm;
        Af[s][0] = pack_bf2(CSCALE * p0[0], CSCALE * p0[1]);
        Af[s][1] = pack_bf2(CSCALE * p1[0], CSCALE * p1[1]);
        Af[s][2] = pack_bf2(CSCALE * p0[2], CSCALE * p0[3]);
        Af[s][3] = pack_bf2(CSCALE * p1[2], CSCALE * p1[3]);
    }

    float sum0 = 0.0f, sum1 = 0.0f;

    float4* az = 0;
    if (write_attn)
        az = (float4*)(out + attn_off + ((size_t)b * LQ + q0) * LK);

    // cp.async destinations: 2 x 16B chunks per thread per tile
    uint32_t dst[2][2];
    int rowc[2], c8c[2];
    #pragma unroll
    for (int i = 0; i < 2; i++) {
        int fi  = tid + i * NT;        // 0..511
        rowc[i] = fi >> 3;
        c8c[i]  = fi & 7;
        dst[0][i] = (uint32_t)__cvta_generic_to_shared(&ks[0][rowc[i]][c8c[i] * 8]);
        dst[1][i] = (uint32_t)__cvta_generic_to_shared(&ks[1][rowc[i]][c8c[i] * 8]);
    }

    // ---- prologue: tile 0 -> buffer 0 ----
    #pragma unroll
    for (int i = 0; i < 2; i++)
        cp_async16(dst[0][i], kbf + (size_t)rowc[i] * DH + c8c[i] * 8);
    CP_COMMIT();
    CP_WAIT0();
    __syncthreads();

    // ================= mainloop: double-buffered pipeline =================
    for (int t = 0; t < NTILES; t++) {
        const int cur = t & 1;

        if (t + 1 < NTILES) {
            const __nv_bfloat16* src = kbf + (size_t)(t + 1) * BK * DH;
            #pragma unroll
            for (int i = 0; i < 2; i++)
                cp_async16(dst[cur ^ 1][i], src + (size_t)rowc[i] * DH + c8c[i] * 8);
            CP_COMMIT();
        }

        if (t > 0 && tid < BQ)
            tilemax[tid][t - 1] = fmaxf(tmstage[cur ^ 1][0][tid],
                                        tmstage[cur ^ 1][1][tid]);

        float acc[4][4];
        #pragma unroll
        for (int nc = 0; nc < 4; nc++)
            #pragma unroll
            for (int c = 0; c < 4; c++) acc[nc][c] = 0.0f;

        #pragma unroll
        for (int nc = 0; nc < 4; nc++) {
            const __nv_bfloat16* rp = &ks[cur][nh * 32 + nc * 8 + l4][lm * 4];
            #pragma unroll
            for (int s = 0; s < 4; s++) {
                // one LDS.64: 4 bf16 = physical d {4lm..4lm+3} of slice s
                unsigned long long bv = *(const unsigned long long*)(rp + s * 16);
                mma_bf16(acc[nc], Af[s][0], Af[s][1], Af[s][2], Af[s][3],
                         (unsigned)(bv & 0xffffffffu), (unsigned)(bv >> 32));
            }
        }

        // epilogue: max + exp-sum (acc already scaled)
        float tm0 = -1e30f, tm1 = -1e30f;
        #pragma unroll
        for (int nc = 0; nc < 4; nc++) {
            tm0 = fmaxf(tm0, fmaxf(acc[nc][0], acc[nc][1]));
            tm1 = fmaxf(tm1, fmaxf(acc[nc][2], acc[nc][3]));
            sum0 += ex2a(acc[nc][0]) + ex2a(acc[nc][1]);
            sum1 += ex2a(acc[nc][2]) + ex2a(acc[nc][3]);
        }
        #pragma unroll
        for (int off = 1; off <= 2; off <<= 1) {
            tm0 = fmaxf(tm0, __shfl_xor_sync(0xffffffffu, tm0, off));
            tm1 = fmaxf(tm1, __shfl_xor_sync(0xffffffffu, tm1, off));
        }
        if (lm == 0) { tmstage[cur][nh][r0] = tm0; tmstage[cur][nh][r1] = tm1; }

        if (write_attn) {
            float4* azc = az + (size_t)t * (BQ * BK / 4);
            #pragma unroll
            for (int j = 0; j < 4; j++)
                azc[tid + j * NT] = make_float4(0.f, 0.f, 0.f, 0.f);
        }

        if (t + 1 < NTILES) CP_WAIT0();
        __syncthreads();
    }
    if (tid < BQ)
        tilemax[tid][NTILES - 1] = fmaxf(tmstage[(NTILES - 1) & 1][0][tid],
                                         tmstage[(NTILES - 1) & 1][1][tid]);

    #pragma unroll
    for (int off = 1; off <= 2; off <<= 1) {
        sum0 += __shfl_xor_sync(0xffffffffu, sum0, off);
        sum1 += __shfl_xor_sync(0xffffffffu, sum1, off);
    }
    if (lm == 0) { rs[nh][r0] = sum0; rs[nh][r1] = sum1; }
    __syncthreads();

    if (tid < BQ) rowsum[tid] = rs[0][tid] + rs[1][tid];
    __syncthreads();

    // ===== repair: sector-clean exact fp32 argmax (unchanged from R15) =====
    #pragma unroll 1
    for (int rr8 = 0; rr8 < BQ / 8; rr8++) {
        const int r = w * 8 + rr8;

        const float tmv = tilemax[r][lane];
        float best = tmv;
        #pragma unroll
        for (int off = 16; off > 0; off >>= 1)
            best = fmaxf(best, __shfl_xor_sync(0xffffffffu, best, off));
        const float thr = best - EPS_S;

        const float4 qv = *(const float4*)(qb + (size_t)r * DH + (lane & 15) * 4);

        float bm = -1e30f;
        int   bi = 0;
        #pragma unroll 1
        for (int t = 0; t < NTILES; t++) {
            if (__shfl_sync(0xffffffffu, tmv, t) < thr) continue;   // warp-uniform
            const float* kt = kb + (size_t)t * BK * DH;
            #pragma unroll 4
            for (int rr = 0; rr < 32; rr++) {
                const int col = rr * 2 + (lane >> 4);
                const float4 kv = *(const float4*)(kt + (size_t)col * DH + (lane & 15) * 4);
                float p = fmaf(qv.x, kv.x, fmaf(qv.y, kv.y,
                          fmaf(qv.z, kv.z, qv.w * kv.w)));
                p += __shfl_xor_sync(0xffffffffu, p, 8, 16);
                p += __shfl_xor_sync(0xffffffffu, p, 4, 16);
                p += __shfl_xor_sync(0xffffffffu, p, 2, 16);
                p += __shfl_xor_sync(0xffffffffu, p, 1, 16);
                if (p > bm) { bm = p; bi = t * BK + col; }
            }
        }
        #pragma unroll
        for (int off = 16; off > 0; off >>= 1) {
            float om = __shfl_xor_sync(0xffffffffu, bm, off);
            int   oi = __shfl_xor_sync(0xffffffffu, bi, off);
            if (om > bm || (om == bm && oi < bi)) { bm = om; bi = oi; }
        }
        if (lane == 0) {
            float p = ex2a(bm * CSCALE) / rowsum[r];
            pval[r] = p;
            widx[r] = bi;
            if (write_attn)
                out[attn_off + ((size_t)b * LQ + q0 + r) * LK + bi] = p;
        }
    }
    __syncthreads();

    // ================= dense output =================
    if (write_out) {
        #pragma unroll
        for (int i = tid; i < BQ * (DH / 4); i += NT) {
            const int r = i >> 4;
            const int c = i & 15;
            const float p = pval[r];
            const float4 vv = *(const float4*)(v + ((size_t)b * LK + widx[r]) * DH + c * 4);
            float4 o;
            o.x = p * vv.x; o.y = p * vv.y; o.z = p * vv.z; o.w = p * vv.w;
            *(float4*)(out + ((size_t)b * LQ + q0 + r) * DH + c * 4) = o;
        }
    }
}

extern "C" void kernel_launch(void* const* d_in, const int* in_sizes, int n_in,
                              void* d_out, int out_size)
{
    const float* q = (const float*)d_in[0];
    const float* k = (const float*)d_in[1];
    const float* v = (const float*)d_in[2];
    float* out = (float*)d_out;

    int wout = 0, wattn = 0;
    long long aoff = 0;
    size_t osz = (size_t)out_size;
    if (osz == OUT_ELEMS + ATTN_ELEMS) { wout = 1; wattn = 1; aoff = (long long)OUT_ELEMS; }
    else if (osz == ATTN_ELEMS)        { wattn = 1; aoff = 0; }
    else                               { wout = 1; }

    // pre-pass: K -> bf16 scratch (stream-ordered before the main kernel)
    cvt_k_kernel<<<2048, 256>>>(k);

    dim3 grid(LQ / BQ, BATCH);
    wta_attn16_kernel<<<grid, NT>>>(q, k, v, out, wout, wattn, aoff);
}

// round 17
// speedup vs baseline: 1.6575x; 1.0877x over previous
#include <cuda_runtime.h>
#include <cuda_bf16.h>
#include <stdint.h>

// Problem constants
#define BATCH 16
#define LQ 2048
#define LK 2048
#define DH 64

#define BQ 32                // halved: 1024 blocks -> fine-grained wave balance
#define BK 64
#define NT 128               // 4 warps
#define NTILES (LK / BK)     // 32
#define KROWB 80             // bf16 k row stride (160 B): LDS.64 conflict-free

#define OUT_ELEMS  ((size_t)BATCH * LQ * DH)   // 2,097,152
#define ATTN_ELEMS ((size_t)BATCH * LQ * LK)   // 67,108,864

#define CSCALE 0.18033688011112042f            // 0.125 * log2(e)
#define EPS_S (0.15f * CSCALE)                 // repair threshold (scaled units)

// 4 MB bf16 copy of K (rna) — device scratch, filled by pre-pass kernel.
__device__ __align__(16) __nv_bfloat16 g_kbf[(size_t)BATCH * LK * DH];

__device__ __forceinline__ float ex2a(float x) {
    float r; asm("ex2.approx.ftz.f32 %0, %1;" : "=f"(r) : "f"(x)); return r;
}
__device__ __forceinline__ unsigned pack_bf2(float lo, float hi) {
    __nv_bfloat162 t = __floats2bfloat162_rn(lo, hi);
    return *(unsigned*)&t;
}
__device__ __forceinline__ void mma_bf16(float c[4],
                                         unsigned a0, unsigned a1, unsigned a2, unsigned a3,
                                         unsigned b0, unsigned b1) {
    asm volatile("mma.sync.aligned.m16n8k16.row.col.f32.bf16.bf16.f32 "
                 "{%0,%1,%2,%3}, {%4,%5,%6,%7}, {%8,%9}, {%0,%1,%2,%3};"
                 : "+f"(c[0]), "+f"(c[1]), "+f"(c[2]), "+f"(c[3])
                 : "r"(a0), "r"(a1), "r"(a2), "r"(a3), "r"(b0), "r"(b1));
}
__device__ __forceinline__ void cp_async16(uint32_t dst_smem, const void* src) {
    asm volatile("cp.async.cg.shared.global [%0], [%1], 16;"
                 :: "r"(dst_smem), "l"(src) : "memory");
}
#define CP_COMMIT() asm volatile("cp.async.commit_group;" ::: "memory")
#define CP_WAIT0()  asm volatile("cp.async.wait_group 0;" ::: "memory")

// ---------- pre-pass: K fp32 -> bf16 (rna) ----------
__global__ __launch_bounds__(256)
void cvt_k_kernel(const float* __restrict__ k)
{
    size_t i = (size_t)blockIdx.x * blockDim.x + threadIdx.x;
    float4 w = ((const float4*)k)[i];
    __nv_bfloat162 lo = __floats2bfloat162_rn(w.x, w.y);
    __nv_bfloat162 hi = __floats2bfloat162_rn(w.z, w.w);
    ((__nv_bfloat162*)g_kbf)[i * 2 + 0] = lo;
    ((__nv_bfloat162*)g_kbf)[i * 2 + 1] = hi;
}

__global__ __launch_bounds__(NT)
void wta_attn17_kernel(const float* __restrict__ q,
                       const float* __restrict__ k,
                       const float* __restrict__ v,
                       float* __restrict__ out,
                       int write_out, int write_attn, long long attn_off)
{
    __shared__ __nv_bfloat16 ks[2][BK][KROWB]; // 20.5 KB double-buffered bf16 k tiles
    __shared__ float tilemax[BQ][NTILES];      //  4  KB (scaled units)
    __shared__ float tmstage[2][2][BQ];
    __shared__ float rs[2][BQ];
    __shared__ float rowsum[BQ];
    __shared__ float pval[BQ];
    __shared__ int   widx[BQ];

    const int b    = blockIdx.y;
    const int q0   = blockIdx.x * BQ;
    const int tid  = threadIdx.x;
    const int w    = tid >> 5;     // 0..3
    const int lane = tid & 31;
    const int wg   = w & 1;        // row group (16 rows each)
    const int nh   = w >> 1;       // col half (32 cols each)
    const int l4   = lane >> 2;
    const int lm   = lane & 3;

    const float* qb = q + ((size_t)b * LQ + q0) * DH;
    const float* kb = k + (size_t)b * LK * DH;
    const __nv_bfloat16* kbf = g_kbf + (size_t)b * LK * DH;

    const int r0 = wg * 16 + l4;
    const int r1 = r0 + 8;

    // ---- A fragments (bf16, C folded, permuted K-index) ----
    unsigned Af[4][4];
    #pragma unroll
    for (int s = 0; s < 4; s++) {
        const float* p0 = qb + (size_t)r0 * DH + s * 16 + 4 * lm;
        const float* p1 = qb + (size_t)r1 * DH + s * 16 + 4 * lm;
        Af[s][0] = pack_bf2(CSCALE * p0[0], CSCALE * p0[1]);
        Af[s][1] = pack_bf2(CSCALE * p1[0], CSCALE * p1[1]);
        Af[s][2] = pack_bf2(CSCALE * p0[2], CSCALE * p0[3]);
        Af[s][3] = pack_bf2(CSCALE * p1[2], CSCALE * p1[3]);
    }

    float sum0 = 0.0f, sum1 = 0.0f;

    float4* az = 0;
    if (write_attn)
        az = (float4*)(out + attn_off + ((size_t)b * LQ + q0) * LK);

    // cp.async destinations: 4 x 16B chunks per thread per tile (8 KB tile)
    uint32_t dst[2][4];
    int rowc[4], c8c[4];
    #pragma unroll
    for (int i = 0; i < 4; i++) {
        int fi  = tid + i * NT;        // 0..511
        rowc[i] = fi >> 3;
        c8c[i]  = fi & 7;
        dst[0][i] = (uint32_t)__cvta_generic_to_shared(&ks[0][rowc[i]][c8c[i] * 8]);
        dst[1][i] = (uint32_t)__cvta_generic_to_shared(&ks[1][rowc[i]][c8c[i] * 8]);
    }

    // ---- prologue: tile 0 -> buffer 0 ----
    #pragma unroll
    for (int i = 0; i < 4; i++)
        cp_async16(dst[0][i], kbf + (size_t)rowc[i] * DH + c8c[i] * 8);
    CP_COMMIT();
    CP_WAIT0();
    __syncthreads();

    // ================= mainloop: double-buffered pipeline =================
    for (int t = 0; t < NTILES; t++) {
        const int cur = t & 1;

        if (t + 1 < NTILES) {
            const __nv_bfloat16* src = kbf + (size_t)(t + 1) * BK * DH;
            #pragma unroll
            for (int i = 0; i < 4; i++)
                cp_async16(dst[cur ^ 1][i], src + (size_t)rowc[i] * DH + c8c[i] * 8);
            CP_COMMIT();
        }

        if (t > 0 && tid < BQ)
            tilemax[tid][t - 1] = fmaxf(tmstage[cur ^ 1][0][tid],
                                        tmstage[cur ^ 1][1][tid]);

        float acc[4][4];
        #pragma unroll
        for (int nc = 0; nc < 4; nc++)
            #pragma unroll
            for (int c = 0; c < 4; c++) acc[nc][c] = 0.0f;

        #pragma unroll
        for (int nc = 0; nc < 4; nc++) {
            const __nv_bfloat16* rp = &ks[cur][nh * 32 + nc * 8 + l4][lm * 4];
            #pragma unroll
            for (int s = 0; s < 4; s++) {
                unsigned long long bv = *(const unsigned long long*)(rp + s * 16);
                mma_bf16(acc[nc], Af[s][0], Af[s][1], Af[s][2], Af[s][3],
                         (unsigned)(bv & 0xffffffffu), (unsigned)(bv >> 32));
            }
        }

        // epilogue: max + exp-sum (acc already scaled)
        float tm0 = -1e30f, tm1 = -1e30f;
        #pragma unroll
        for (int nc = 0; nc < 4; nc++) {
            tm0 = fmaxf(tm0, fmaxf(acc[nc][0], acc[nc][1]));
            tm1 = fmaxf(tm1, fmaxf(acc[nc][2], acc[nc][3]));
            sum0 += ex2a(acc[nc][0]) + ex2a(acc[nc][1]);
            sum1 += ex2a(acc[nc][2]) + ex2a(acc[nc][3]);
        }
        #pragma unroll
        for (int off = 1; off <= 2; off <<= 1) {
            tm0 = fmaxf(tm0, __shfl_xor_sync(0xffffffffu, tm0, off));
            tm1 = fmaxf(tm1, __shfl_xor_sync(0xffffffffu, tm1, off));
        }
        if (lm == 0) { tmstage[cur][nh][r0] = tm0; tmstage[cur][nh][r1] = tm1; }

        // interleaved zero-fill of this tile's attn chunk (32 x 64)
        if (write_attn) {
            float4* azc = az + (size_t)t * (BQ * BK / 4);   // 512 float4
            #pragma unroll
            for (int j = 0; j < 4; j++)
                azc[tid + j * NT] = make_float4(0.f, 0.f, 0.f, 0.f);
        }

        if (t + 1 < NTILES) CP_WAIT0();
        __syncthreads();
    }
    if (tid < BQ)
        tilemax[tid][NTILES - 1] = fmaxf(tmstage[(NTILES - 1) & 1][0][tid],
                                         tmstage[(NTILES - 1) & 1][1][tid]);

    #pragma unroll
    for (int off = 1; off <= 2; off <<= 1) {
        sum0 += __shfl_xor_sync(0xffffffffu, sum0, off);
        sum1 += __shfl_xor_sync(0xffffffffu, sum1, off);
    }
    if (lm == 0) { rs[nh][r0] = sum0; rs[nh][r1] = sum1; }
    __syncthreads();

    if (tid < BQ) rowsum[tid] = rs[0][tid] + rs[1][tid];
    __syncthreads();

    // ===== repair: sector-clean exact fp32 argmax (1 warp per row) =====
    #pragma unroll 1
    for (int rr8 = 0; rr8 < BQ / 4; rr8++) {     // 8 rows per warp
        const int r = w * 8 + rr8;

        const float tmv = tilemax[r][lane];
        float best = tmv;
        #pragma unroll
        for (int off = 16; off > 0; off >>= 1)
            best = fmaxf(best, __shfl_xor_sync(0xffffffffu, best, off));
        const float thr = best - EPS_S;

        const float4 qv = *(const float4*)(qb + (size_t)r * DH + (lane & 15) * 4);

        float bm = -1e30f;
        int   bi = 0;
        #pragma unroll 1
        for (int t = 0; t < NTILES; t++) {
            if (__shfl_sync(0xffffffffu, tmv, t) < thr) continue;   // warp-uniform
            const float* kt = kb + (size_t)t * BK * DH;
            #pragma unroll 4
            for (int rr = 0; rr < 32; rr++) {
                const int col = rr * 2 + (lane >> 4);
                const float4 kv = *(const float4*)(kt + (size_t)col * DH + (lane & 15) * 4);
                float p = fmaf(qv.x, kv.x, fmaf(qv.y, kv.y,
                          fmaf(qv.z, kv.z, qv.w * kv.w)));
                p += __shfl_xor_sync(0xffffffffu, p, 8, 16);
                p += __shfl_xor_sync(0xffffffffu, p, 4, 16);
                p += __shfl_xor_sync(0xffffffffu, p, 2, 16);
                p += __shfl_xor_sync(0xffffffffu, p, 1, 16);
                if (p > bm) { bm = p; bi = t * BK + col; }
            }
        }
        #pragma unroll
        for (int off = 16; off > 0; off >>= 1) {
            float om = __shfl_xor_sync(0xffffffffu, bm, off);
            int   oi = __shfl_xor_sync(0xffffffffu, bi, off);
            if (om > bm || (om == bm && oi < bi)) { bm = om; bi = oi; }
        }
        if (lane == 0) {
            float p = ex2a(bm * CSCALE) / rowsum[r];
            pval[r] = p;
            widx[r] = bi;
            if (write_attn)
                out[attn_off + ((size_t)b * LQ + q0 + r) * LK + bi] = p;
        }
    }
    __syncthreads();

    // ================= dense output =================
    if (write_out) {
        #pragma unroll
        for (int i = tid; i < BQ * (DH / 4); i += NT) {
            const int r = i >> 4;
            const int c = i & 15;
            const float p = pval[r];
            const float4 vv = *(const float4*)(v + ((size_t)b * LK + widx[r]) * DH + c * 4);
            float4 o;
            o.x = p * vv.x; o.y = p * vv.y; o.z = p * vv.z; o.w = p * vv.w;
            *(float4*)(out + ((size_t)b * LQ + q0 + r) * DH + c * 4) = o;
        }
    }
}

extern "C" void kernel_launch(void* const* d_in, const int* in_sizes, int n_in,
                              void* d_out, int out_size)
{
    const float* q = (const float*)d_in[0];
    const float* k = (const float*)d_in[1];
    const float* v = (const float*)d_in[2];
    float* out = (float*)d_out;

    int wout = 0, wattn = 0;
    long long aoff = 0;
    size_t osz = (size_t)out_size;
    if (osz == OUT_ELEMS + ATTN_ELEMS) { wout = 1; wattn = 1; aoff = (long long)OUT_ELEMS; }
    else if (osz == ATTN_ELEMS)        { wattn = 1; aoff = 0; }
    else                               { wout = 1; }

    // pre-pass: K -> bf16 scratch (stream-ordered before the main kernel)
    cvt_k_kernel<<<2048, 256>>>(k);

    dim3 grid(LQ / BQ, BATCH);   // 64 x 16 = 1024 blocks
    wta_attn17_kernel<<<grid, NT>>>(q, k, v, out, wout, wattn, aoff);
}